// round 15
// baseline (speedup 1.0000x reference)
#include <cuda_runtime.h>
#include <cuda_bf16.h>
#include <math.h>
#include <stdint.h>

#define BB 16
#define TT 4096
#define DINNER 384
#define NH 8
#define HD 48
#define DS 64
#define DPROJ 904
#define NC 64
#define CS 64
#define MIXD 32

// ---------------- scratch (static device arrays; no runtime alloc) ----------
__device__ float g_W1[4 * DPROJ];            // w_in @ w_inproj
__device__ float g_mvec[BB * DPROJ];         // (b_in + relu(mic)) @ w_inproj
__device__ uint32_t g_W2bt32[32 * 192];      // bf16x2 [o][dpair]
__device__ float g_hb[BB * 192];
__device__ float g_A[NH];
__device__ uint32_t g_xbfT[(size_t)BB * NC * 384 * 32]; // x bf16, t-minor: [b][c][p][t-pair]
__device__ float g_bc[(size_t)BB * TT * 128];      // B(64) | C(64) fp32
__device__ float g_dt[(size_t)BB * TT * NH];
__device__ float g_la[(size_t)BB * TT * NH];       // log-decay = dt*A
__device__ uint32_t g_Sbf[(size_t)128 * NC * HD * 32]; // chunk states bf16x2 (pairs along n) -> h_in in place
__device__ float g_Dc[128 * NC];
__device__ uint32_t g_ybf32[(size_t)BB * TT * 192];    // gated y, bf16x2
__device__ float g_rstd[BB * TT];
__device__ float g_part[2048 * MIXD];

__device__ __forceinline__ float siluf(float v) {
    if (fabsf(v) < 0.25f) {
        float z2 = v * v;
        float sig = 0.5f + v * (0.25f + z2 * (-(1.f / 48.f) + z2 * (1.f / 480.f)));
        return v * sig;
    }
    return __fdividef(v, 1.f + __expf(-v));
}
__device__ __forceinline__ float softplusf(float v) { return v > 20.f ? v : __logf(1.f + __expf(v)); }

__device__ __forceinline__ uint32_t packbf(float lo, float hi) {
    uint32_t w;
    asm("cvt.rn.bf16x2.f32 %0, %1, %2;" : "=r"(w) : "f"(hi), "f"(lo));
    return w;
}
__device__ __forceinline__ float2 unpackbf(uint32_t w) {
    return make_float2(__uint_as_float(w << 16), __uint_as_float(w & 0xffff0000u));
}
__device__ __forceinline__ uint16_t bf16b(float v) {
    __nv_bfloat16 h = __float2bfloat16(v);
    return *reinterpret_cast<uint16_t*>(&h);
}

__device__ __forceinline__ void mma16(float d[4], const uint32_t a[4], const uint32_t b[2]) {
    asm volatile(
        "mma.sync.aligned.m16n8k16.row.col.f32.bf16.bf16.f32 "
        "{%0,%1,%2,%3},{%4,%5,%6,%7},{%8,%9},{%0,%1,%2,%3};\n"
        : "+f"(d[0]), "+f"(d[1]), "+f"(d[2]), "+f"(d[3])
        : "r"(a[0]), "r"(a[1]), "r"(a[2]), "r"(a[3]),
          "r"(b[0]), "r"(b[1]));
}

// ---------------- k0a: mic MLP + A ----------------
__global__ void k0a(const float* __restrict__ mic_pos, const float* __restrict__ w_mic,
                    const float* __restrict__ b_mic, const float* __restrict__ b_in,
                    const float* __restrict__ A_log) {
    int tid = threadIdx.x;
    for (int i = tid; i < BB * 192; i += 256) {
        int b = i / 192, d = i % 192;
        float s = b_mic[d];
        #pragma unroll
        for (int j = 0; j < 12; j++) s = fmaf(mic_pos[b * 12 + j], w_mic[j * 192 + d], s);
        g_hb[i] = b_in[d] + fmaxf(s, 0.f);
    }
    if (tid < NH) g_A[tid] = -expf(A_log[tid]);
}

// ---------------- k0b: folded weights ----------------
__global__ void k0b(const float* __restrict__ w_in, const float* __restrict__ w_inproj,
                    const float* __restrict__ w_outproj, const float* __restrict__ w_mix1,
                    const float* __restrict__ norm_w) {
    int i = blockIdx.x * 256 + threadIdx.x;
    if (i < 4 * DPROJ) {
        int j = i / DPROJ, d = i % DPROJ;
        float s = 0.f;
        for (int m = 0; m < 192; m++) s = fmaf(w_in[j * 192 + m], w_inproj[m * DPROJ + d], s);
        g_W1[i] = s;
    } else if (i < 4 * DPROJ + BB * DPROJ) {
        int ii = i - 4 * DPROJ;
        int b = ii / DPROJ, d = ii % DPROJ;
        float s = 0.f;
        for (int m = 0; m < 192; m++) s = fmaf(g_hb[b * 192 + m], w_inproj[m * DPROJ + d], s);
        g_mvec[ii] = s;
    } else if (i < 4 * DPROJ + BB * DPROJ + 32 * 192) {
        int ii = i - (4 * DPROJ + BB * DPROJ);
        int o = ii / 192, kw = ii % 192;
        int d0 = 2 * kw, d1 = d0 + 1;
        float s0 = 0.f, s1 = 0.f;
        for (int m = 0; m < 192; m++) {
            s0 = fmaf(w_outproj[d0 * 192 + m], w_mix1[m * MIXD + o], s0);
            s1 = fmaf(w_outproj[d1 * 192 + m], w_mix1[m * MIXD + o], s1);
        }
        g_W2bt32[o * 192 + kw] = packbf(s0 * norm_w[d0], s1 * norm_w[d1]);
    }
}

// ---------------- k1: fused inproj + conv4 + silu + dt/la + x transpose ----
// grid (32, 16) block 128 : thread = one t
__global__ void k1(const float* __restrict__ x, const float* __restrict__ conv_w,
                   const float* __restrict__ conv_b, const float* __restrict__ dt_bias) {
    __shared__ float sW1[4 * 520];   // proj dims 384..903
    __shared__ float smv[520];
    __shared__ float scw[512 * 4];
    __shared__ float scb[512];
    __shared__ float sx4[131 * 4];
    __shared__ float sraw[131 * 33];
    __shared__ uint16_t sT[32 * 128];   // transpose buffer: [p-chunk 32][t 128]

    int tid = threadIdx.x;
    int b = blockIdx.y;
    int t0 = blockIdx.x * 128;

    for (int i = tid; i < 4 * 520; i += 128) sW1[i] = g_W1[(i / 520) * DPROJ + 384 + (i % 520)];
    for (int i = tid; i < 520; i += 128) smv[i] = g_mvec[b * DPROJ + 384 + i];
    for (int i = tid; i < 512 * 4; i += 128) scw[i] = conv_w[i];
    for (int i = tid; i < 512; i += 128) scb[i] = conv_b[i];
    for (int i = tid; i < 131 * 4; i += 128) {
        int r = i >> 2, j = i & 3;
        int t = t0 + r - 3;
        sx4[i] = (t >= 0) ? x[((size_t)b * TT + t) * 4 + j] : 0.f;
    }

    int t = t0 + tid;
    int cBase = blockIdx.x * 2;
    for (int c16 = 0; c16 < 16; c16++) {
        __syncthreads();
        for (int i = tid; i < 131 * 32; i += 128) {
            int r = i >> 5, dc = i & 31;
            int dd = c16 * 32 + dc;
            float v = 0.f;
            if (t0 + r - 3 >= 0) {
                v = smv[dd];
                #pragma unroll
                for (int j = 0; j < 4; j++) v = fmaf(sx4[r * 4 + j], sW1[j * 520 + dd], v);
            }
            sraw[r * 33 + dc] = v;
        }
        __syncthreads();
        float v[32];
        #pragma unroll
        for (int dc = 0; dc < 32; dc++) {
            int dd = c16 * 32 + dc;
            float a = scb[dd];
            #pragma unroll
            for (int k = 0; k < 4; k++) a = fmaf(sraw[(tid + k) * 33 + dc], scw[dd * 4 + k], a);
            v[dc] = siluf(a);
        }
        if (c16 < 12) {
            // transpose to t-minor and write coalesced words
            #pragma unroll
            for (int dc = 0; dc < 32; dc++) sT[dc * 128 + tid] = bf16b(v[dc]);
            __syncthreads();
            const uint32_t* sT32 = (const uint32_t*)sT;
            for (int i = tid; i < 2048; i += 128) {
                int p = i >> 6, wq = i & 63;
                int ch = wq >> 5, tw = wq & 31;
                g_xbfT[(((size_t)b * NC + cBase + ch) * 384 + c16 * 32 + p) * 32 + tw] = sT32[p * 64 + wq];
            }
        } else {
            float* dst = g_bc + ((size_t)b * TT + t) * 128 + (c16 - 12) * 32;
            #pragma unroll
            for (int q = 0; q < 8; q++)
                ((float4*)dst)[q] = make_float4(v[4 * q], v[4 * q + 1], v[4 * q + 2], v[4 * q + 3]);
        }
    }

    // dt path (proj dims 896..903 via sW1 dims 512..519)
    #pragma unroll
    for (int hh = 0; hh < NH; hh++) {
        int dd = 512 + hh;
        float v = smv[dd];
        #pragma unroll
        for (int j = 0; j < 4; j++) v = fmaf(sx4[(tid + 3) * 4 + j], sW1[j * 520 + dd], v);
        float dt = softplusf(v + dt_bias[hh]);
        size_t o = ((size_t)b * TT + t) * NH + hh;
        g_dt[o] = dt;
        g_la[o] = dt * g_A[hh];
    }
}

// ---------------- kA: chunk-local end states via bf16 mma16, all heads/block
// grid (NC, BB) block 192 (6 warps): warp = (p-strip w%3, n-half w/3)
// A = x^T from global, B = wgt-scaled B in smem
__global__ __launch_bounds__(192) void kA() {
    __shared__ uint32_t sBn[64 * 36];   // bf16x2 [n][t-pair] raw B
    __shared__ uint32_t sBw[64 * 36];   // bf16x2 [n][t-pair] wgt-scaled (per head)
    __shared__ float sCS[8 * 64];       // [h][t] inclusive log-decay prefix
    __shared__ float sDT[8 * 64];       // [h][t]
    __shared__ float sWgt[64];

    int c = blockIdx.x, b = blockIdx.y;
    int tid = threadIdx.x;
    int wid = tid >> 5, lane = tid & 31;
    int lq = lane & 3, lh = lane >> 2;
    int t0 = c * CS;
    uint16_t* shB = (uint16_t*)sBn;

    // la/dt for all heads, transpose to [h][t]
    if (tid < 128) {
        const float* lap = g_la + ((size_t)b * TT + t0) * NH;
        const float* dtp = g_dt + ((size_t)b * TT + t0) * NH;
        float4 v = ((const float4*)lap)[tid];
        float4 w = ((const float4*)dtp)[tid];
        int j0 = tid * 4;
        #pragma unroll
        for (int u = 0; u < 4; u++) {
            int j = j0 + u;
            int t = j >> 3, h = j & 7;
            sCS[h * 64 + t] = (&v.x)[u];
            sDT[h * 64 + t] = (&w.x)[u];
        }
    }

    // B staged ONCE as bf16 [n][t] (16-bit transpose stores)
    const float* bp = g_bc + ((size_t)b * TT + t0) * 128;
    for (int i = tid; i < CS * 16; i += 192) {
        int t = i >> 4, nq = i & 15;
        float4 v = ((const float4*)(bp + (size_t)t * 128))[nq];
        int n0 = nq * 4;
        shB[(n0 + 0) * 72 + t] = bf16b(v.x);
        shB[(n0 + 1) * 72 + t] = bf16b(v.y);
        shB[(n0 + 2) * 72 + t] = bf16b(v.z);
        shB[(n0 + 3) * 72 + t] = bf16b(v.w);
    }
    __syncthreads();

    // per-head inclusive log-decay prefix scans (6 warps cover 8 heads)
    for (int hh = wid; hh < NH; hh += 6) {
        float a0 = sCS[hh * 64 + 2 * lane], a1 = sCS[hh * 64 + 2 * lane + 1];
        float ps = a0 + a1;
        #pragma unroll
        for (int off = 1; off < 32; off <<= 1) {
            float v = __shfl_up_sync(0xffffffffu, ps, off);
            if (lane >= off) ps += v;
        }
        sCS[hh * 64 + 2 * lane + 1] = ps;
        sCS[hh * 64 + 2 * lane]     = ps - a1;
    }
    __syncthreads();

    int p0 = (wid % 3) * 16;
    int nb = (wid / 3) * 32;

    for (int h = 0; h < NH; h++) {
        const float* csh = sCS + h * 64;
        const float* dth = sDT + h * 64;
        float cstot = csh[CS - 1];

        if (tid < 64) sWgt[tid] = __expf(cstot - csh[tid]) * dth[tid];
        __syncthreads();

        // scale B by wgt along t (word ops, no scatter)
        for (int i = tid; i < 64 * 32; i += 192) {
            int n = i >> 5, tw = i & 31;
            float2 q = unpackbf(sBn[n * 36 + tw]);
            sBw[n * 36 + tw] = packbf(q.x * sWgt[2 * tw], q.y * sWgt[2 * tw + 1]);
        }
        __syncthreads();

        // S[p][n] = sum_t x[t][p] * Bw[t][n]  (A from global x^T)
        const uint32_t* xT = g_xbfT + (((size_t)b * NC + c) * 384 + h * HD) * 32;
        float acc[4][4];
        #pragma unroll
        for (int j = 0; j < 4; j++)
            #pragma unroll
            for (int e = 0; e < 4; e++) acc[j][e] = 0.f;

        #pragma unroll
        for (int k16 = 0; k16 < CS; k16 += 16) {
            int kw = k16 >> 1;
            uint32_t a[4];
            a[0] = __ldg(&xT[(p0 + lh) * 32 + kw + lq]);
            a[1] = __ldg(&xT[(p0 + lh + 8) * 32 + kw + lq]);
            a[2] = __ldg(&xT[(p0 + lh) * 32 + kw + lq + 4]);
            a[3] = __ldg(&xT[(p0 + lh + 8) * 32 + kw + lq + 4]);
            #pragma unroll
            for (int j = 0; j < 4; j++) {
                int n = nb + 8 * j + lh;
                uint32_t bfr[2];
                bfr[0] = sBw[n * 36 + kw + lq];
                bfr[1] = sBw[n * 36 + kw + lq + 4];
                mma16(acc[j], a, bfr);
            }
        }

        uint32_t* sp = g_Sbf + ((size_t)(b * NH + h) * NC + c) * 1536;
        #pragma unroll
        for (int j = 0; j < 4; j++) {
            int n0 = nb + 8 * j + 2 * lq;
            sp[(p0 + lh) * 32 + (n0 >> 1)]     = packbf(acc[j][0], acc[j][1]);
            sp[(p0 + lh + 8) * 32 + (n0 >> 1)] = packbf(acc[j][2], acc[j][3]);
        }
        if (tid == 0) g_Dc[(b * NH + h) * NC + c] = __expf(cstot);
        __syncthreads();   // sBw/sWgt reads done before next head's writes
    }
}

// ---------------- kB: inter-chunk scan (fp32 regs, bf16 storage) ----------
// grid (128, 4) block 384 : thread owns 2 states (1 word), depth-2 prefetch
__global__ void kB() {
    int bh = blockIdx.x, q = blockIdx.y;
    int tid = threadIdx.x;
    float h0 = 0.f, h1 = 0.f;
    size_t base = (size_t)bh * NC * 1536 + (size_t)q * 384 + tid;
    uint32_t a0 = g_Sbf[base];
    uint32_t a1 = g_Sbf[base + 1536];
    float D0 = g_Dc[bh * NC];
    float D1 = g_Dc[bh * NC + 1];
    for (int c = 0; c < NC; c++) {
        uint32_t* sp = g_Sbf + base + (size_t)c * 1536;
        uint32_t an = 0u;
        float Dn = 0.f;
        if (c + 2 < NC) {
            an = sp[2 * 1536];
            Dn = g_Dc[bh * NC + c + 2];
        }
        float2 p = unpackbf(a0);
        sp[0] = packbf(h0, h1);
        h0 = fmaf(h0, D0, p.x);
        h1 = fmaf(h1, D0, p.y);
        a0 = a1; a1 = an; D0 = D1; D1 = Dn;
    }
}

// ---------------- kC: chunked SSD + fused gating/RMS-stats (all-bf16 mma) --
// grid (NC, BB) block 256 (8 warps), smem ~40.4 KB -> 5 CTAs/SM
// x^T and h_in B-fragments read straight from global.
#define STB 36
#define KC_G    0                        // G bf16 words [t][STB]   (2304)
#define KC_CB   (KC_G + 64 * STB)        // C bf16 [t][n-pair]      (2304)
#define KC_BB   (KC_CB + 64 * STB)       // B bf16 [s][n-pair]      (2304)
#define KC_SCS  (KC_BB + 64 * STB)       // 8*64
#define KC_SDT  (KC_SCS + 512)           // 8*64
#define KC_W1Z  (KC_SDT + 512)           // 4*384
#define KC_MVZ  (KC_W1Z + 1536)          // 384
#define KC_X4   (KC_MVZ + 384)           // 64*4
#define KC_SMEM_FLOATS (KC_X4 + 256)

__global__ __launch_bounds__(256) void kC(const float* __restrict__ D_skip,
                                          const float* __restrict__ xin) {
    extern __shared__ float sm[];
    uint32_t* smu = (uint32_t*)sm;
    float* sCS  = sm + KC_SCS;
    float* sDT  = sm + KC_SDT;
    float* sW1z = sm + KC_W1Z;
    float* smvz = sm + KC_MVZ;
    float* sx4  = sm + KC_X4;

    int c = blockIdx.x, b = blockIdx.y;
    int tid = threadIdx.x;
    int wid = tid >> 5, lane = tid & 31;
    int lq = lane & 3, lh = lane >> 2;
    int t0c = c * CS;

    if (tid < 128) {
        const float* lap = g_la + ((size_t)b * TT + t0c) * NH;
        const float* dtp = g_dt + ((size_t)b * TT + t0c) * NH;
        float4 v = ((const float4*)lap)[tid];
        float4 w = ((const float4*)dtp)[tid];
        int j0 = tid * 4;
        #pragma unroll
        for (int u = 0; u < 4; u++) {
            int j = j0 + u;
            int t = j >> 3, h = j & 7;
            sCS[h * 64 + t] = (&v.x)[u];
            sDT[h * 64 + t] = (&w.x)[u];
        }
    }
    for (int i = tid; i < 4 * DINNER; i += 256) sW1z[i] = g_W1[(i / DINNER) * DPROJ + (i % DINNER)];
    for (int i = tid; i < DINNER; i += 256) smvz[i] = g_mvec[b * DPROJ + i];
    if (tid < 256) {
        int r = tid >> 2, j = tid & 3;
        sx4[tid] = xin[((size_t)b * TT + t0c + r) * 4 + j];
    }

    // B,C load: bf16-packed row layouts [s][n-pair]
    const float* bp = g_bc + ((size_t)b * TT + t0c) * 128;
    for (int i = tid; i < CS * 16; i += 256) {
        int s = i >> 4, nq = i & 15;
        float4 v = ((const float4*)(bp + (size_t)s * 128))[nq];          // B[s][n]
        smu[KC_BB + s * STB + 2 * nq]     = packbf(v.x, v.y);
        smu[KC_BB + s * STB + 2 * nq + 1] = packbf(v.z, v.w);
        float4 w = ((const float4*)(bp + (size_t)s * 128))[nq + 16];     // C[s][n]
        smu[KC_CB + s * STB + 2 * nq]     = packbf(w.x, w.y);
        smu[KC_CB + s * STB + 2 * nq + 1] = packbf(w.z, w.w);
    }
    __syncthreads();

    // per-head inclusive log-decay prefix (warp w = head w)
    {
        float a0 = sCS[wid * 64 + 2 * lane];
        float a1 = sCS[wid * 64 + 2 * lane + 1];
        float ps = a0 + a1;
        #pragma unroll
        for (int off = 1; off < 32; off <<= 1) {
            float v = __shfl_up_sync(0xffffffffu, ps, off);
            if (lane >= off) ps += v;
        }
        sCS[wid * 64 + 2 * lane + 1] = ps;
        sCS[wid * 64 + 2 * lane]     = ps - a1;
    }

    int t0 = (wid & 3) * 16;
    int sb = (wid >> 2) * 32;
    int pb = (wid >> 2) * 24;

    float xr0[4], xr1[4];
    #pragma unroll
    for (int u = 0; u < 4; u++) {
        xr0[u] = sx4[(t0 + lh) * 4 + u];
        xr1[u] = sx4[(t0 + lh + 8) * 4 + u];
    }
    __syncthreads();   // prefix scan visible to all warps

    // GEMM1 (bf16, shared across heads): Graw[t][s] = sum_n C[t][n]*B[s][n]
    float g1[4][4];
    #pragma unroll
    for (int j = 0; j < 4; j++)
        #pragma unroll
        for (int e = 0; e < 4; e++) g1[j][e] = 0.f;

    #pragma unroll
    for (int k16 = 0; k16 < DS; k16 += 16) {
        int kw = k16 >> 1;
        uint32_t a[4];
        a[0] = smu[KC_CB + (t0 + lh) * STB + kw + lq];
        a[1] = smu[KC_CB + (t0 + lh + 8) * STB + kw + lq];
        a[2] = smu[KC_CB + (t0 + lh) * STB + kw + lq + 4];
        a[3] = smu[KC_CB + (t0 + lh + 8) * STB + kw + lq + 4];
        #pragma unroll
        for (int j = 0; j < 4; j++) {
            int s = sb + 8 * j + lh;
            uint32_t bfr[2];
            bfr[0] = smu[KC_BB + s * STB + kw + lq];
            bfr[1] = smu[KC_BB + s * STB + kw + lq + 4];
            mma16(g1[j], a, bfr);
        }
    }

    float ss0 = 0.f, ss1 = 0.f;
    uint32_t* ybase = g_ybf32 + ((size_t)b * TT + t0c) * 192;

    for (int h = 0; h < NH; h++) {
        __syncthreads();   // prior head's reads of G done

        // mask+scale Graw with this head's decay, store bf16 G [t][s-pair]
        const float* csh = sCS + h * 64;
        const float* dth = sDT + h * 64;
        {
            float cs_r0 = csh[t0 + lh], cs_r1 = csh[t0 + lh + 8];
            #pragma unroll
            for (int j = 0; j < 4; j++) {
                int c0 = sb + 8 * j + 2 * lq;
                float cs_c0 = csh[c0], cs_c1 = csh[c0 + 1];
                float dt_c0 = dth[c0], dt_c1 = dth[c0 + 1];
                int r0 = t0 + lh, r1 = r0 + 8;
                float m00 = (c0 <= r0) ? __expf(cs_r0 - cs_c0) * dt_c0 : 0.f;
                float m01 = (c0 + 1 <= r0) ? __expf(cs_r0 - cs_c1) * dt_c1 : 0.f;
                float m10 = (c0 <= r1) ? __expf(cs_r1 - cs_c0) * dt_c0 : 0.f;
                float m11 = (c0 + 1 <= r1) ? __expf(cs_r1 - cs_c1) * dt_c1 : 0.f;
                int cw = c0 >> 1;
                smu[KC_G + r0 * STB + cw] = packbf(g1[j][0] * m00, g1[j][1] * m01);
                smu[KC_G + r1 * STB + cw] = packbf(g1[j][2] * m10, g1[j][3] * m11);
            }
        }
        __syncthreads();

        // GEMM2 (bf16): Yintra[t][p] = sum_s G[t][s]*x[s][p]   (x^T from global)
        // GEMM3 (bf16): Yinter[t][p] = sum_n C[t][n]*hin[n][p] (h_in from global)
        float accA[3][4], accB[3][4];
        #pragma unroll
        for (int j = 0; j < 3; j++)
            #pragma unroll
            for (int e = 0; e < 4; e++) { accA[j][e] = 0.f; accB[j][e] = 0.f; }

        const uint32_t* xT = g_xbfT + (((size_t)b * NC + c) * 384 + h * HD) * 32;
        const uint32_t* hp = g_Sbf + ((size_t)(b * NH + h) * NC + c) * 1536;
        #pragma unroll
        for (int k16 = 0; k16 < 64; k16 += 16) {
            int kw = k16 >> 1;
            uint32_t a[4];
            a[0] = smu[KC_G + (t0 + lh) * STB + kw + lq];
            a[1] = smu[KC_G + (t0 + lh + 8) * STB + kw + lq];
            a[2] = smu[KC_G + (t0 + lh) * STB + kw + lq + 4];
            a[3] = smu[KC_G + (t0 + lh + 8) * STB + kw + lq + 4];
            #pragma unroll
            for (int j = 0; j < 3; j++) {
                int p = pb + 8 * j + lh;
                uint32_t bfr[2];
                bfr[0] = __ldg(&xT[p * 32 + kw + lq]);
                bfr[1] = __ldg(&xT[p * 32 + kw + lq + 4]);
                mma16(accA[j], a, bfr);
            }
            uint32_t a2[4];
            a2[0] = smu[KC_CB + (t0 + lh) * STB + kw + lq];
            a2[1] = smu[KC_CB + (t0 + lh + 8) * STB + kw + lq];
            a2[2] = smu[KC_CB + (t0 + lh) * STB + kw + lq + 4];
            a2[3] = smu[KC_CB + (t0 + lh + 8) * STB + kw + lq + 4];
            #pragma unroll
            for (int j = 0; j < 3; j++) {
                int p = pb + 8 * j + lh;
                uint32_t bfr[2];
                bfr[0] = __ldg(hp + p * 32 + kw + lq);
                bfr[1] = __ldg(hp + p * 32 + kw + lq + 4);
                mma16(accB[j], a2, bfr);
            }
        }

        // epilogue: y = intra + exp(cs)*inter + D*x; gate; accumulate ss; store bf16
        float dskip = D_skip[h];
        float et0 = __expf(csh[t0 + lh]);
        float et1 = __expf(csh[t0 + lh + 8]);
        int r0 = t0 + lh, r1 = r0 + 8;
        #pragma unroll
        for (int j = 0; j < 3; j++) {
            int p0c = pb + 8 * j + 2 * lq;
            int dd = h * HD + p0c;
            float2 xa0 = unpackbf(__ldg(&xT[p0c * 32 + (r0 >> 1)]));
            float2 xb0 = unpackbf(__ldg(&xT[(p0c + 1) * 32 + (r0 >> 1)]));
            float2 xa1 = unpackbf(__ldg(&xT[p0c * 32 + (r1 >> 1)]));
            float2 xb1 = unpackbf(__ldg(&xT[(p0c + 1) * 32 + (r1 >> 1)]));
            float x00 = (r0 & 1) ? xa0.y : xa0.x;
            float x01 = (r0 & 1) ? xb0.y : xb0.x;
            float x10 = (r1 & 1) ? xa1.y : xa1.x;
            float x11 = (r1 & 1) ? xb1.y : xb1.x;
            float y00 = accA[j][0] + et0 * accB[j][0] + dskip * x00;
            float y01 = accA[j][1] + et0 * accB[j][1] + dskip * x01;
            float y10 = accA[j][2] + et1 * accB[j][2] + dskip * x10;
            float y11 = accA[j][3] + et1 * accB[j][3] + dskip * x11;
            float w0a = sW1z[dd],            w0b = sW1z[dd + 1];
            float w1a = sW1z[DINNER + dd],   w1b = sW1z[DINNER + dd + 1];
            float w2a = sW1z[2*DINNER + dd], w2b = sW1z[2*DINNER + dd + 1];
            float w3a = sW1z[3*DINNER + dd], w3b = sW1z[3*DINNER + dd + 1];
            float mva = smvz[dd], mvb = smvz[dd + 1];
            float za0 = fmaf(xr0[3], w3a, fmaf(xr0[2], w2a, fmaf(xr0[1], w1a, fmaf(xr0[0], w0a, mva))));
            float zb0 = fmaf(xr0[3], w3b, fmaf(xr0[2], w2b, fmaf(xr0[1], w1b, fmaf(xr0[0], w0b, mvb))));
            float za1 = fmaf(xr1[3], w3a, fmaf(xr1[2], w2a, fmaf(xr1[1], w1a, fmaf(xr1[0], w0a, mva))));
            float zb1 = fmaf(xr1[3], w3b, fmaf(xr1[2], w2b, fmaf(xr1[1], w1b, fmaf(xr1[0], w0b, mvb))));
            float g00 = y00 * siluf(za0);
            float g01 = y01 * siluf(zb0);
            float g10 = y10 * siluf(za1);
            float g11 = y11 * siluf(zb1);
            ss0 = fmaf(g00, g00, fmaf(g01, g01, ss0));
            ss1 = fmaf(g10, g10, fmaf(g11, g11, ss1));
            ybase[(size_t)r0 * 192 + (dd >> 1)] = packbf(g00, g01);
            ybase[(size_t)r1 * 192 + (dd >> 1)] = packbf(g10, g11);
        }
    }

    // row sum-of-squares -> rstd   (reuse sCS region)
    __syncthreads();
    ss0 += __shfl_xor_sync(0xffffffffu, ss0, 1);
    ss0 += __shfl_xor_sync(0xffffffffu, ss0, 2);
    ss1 += __shfl_xor_sync(0xffffffffu, ss1, 1);
    ss1 += __shfl_xor_sync(0xffffffffu, ss1, 2);
    if (lq == 0) {
        sCS[(wid >> 2) * 64 + t0 + lh]     = ss0;
        sCS[(wid >> 2) * 64 + t0 + lh + 8] = ss1;
    }
    __syncthreads();
    if (tid < 64) {
        float s = sCS[tid] + sCS[64 + tid];
        g_rstd[(size_t)b * TT + t0c + tid] = rsqrtf(s * (1.f / DINNER) + 1e-5f);
    }
}

// ---------------- kD2: bf16 mma GEMM(W2) + rstd + mix2 + partial ----------
// grid (32, BB) block 256 (8 warps), 128 rows/block
__global__ __launch_bounds__(256) void kD2(const float* __restrict__ b_mix1,
                   const float* __restrict__ w_mix2, const float* __restrict__ b_mix2) {
    __shared__ float sm1[128 * 33];
    __shared__ float swm2[MIXD * MIXD];

    int tid = threadIdx.x;
    int wid = tid >> 5, lane = tid & 31;
    int lq = lane & 3, lh = lane >> 2;
    int b = blockIdx.y;
    int t0 = blockIdx.x * 128;

    for (int i = tid; i < MIXD * MIXD; i += 256) swm2[i] = w_mix2[i];

    const uint32_t* arow = g_ybf32 + ((size_t)b * TT + t0 + wid * 16) * 192;
    float acc[4][4];
    #pragma unroll
    for (int j = 0; j < 4; j++)
        #pragma unroll
        for (int e = 0; e < 4; e++) acc[j][e] = 0.f;

    #pragma unroll 4
    for (int k16 = 0; k16 < DINNER; k16 += 16) {
        int kw = k16 >> 1;
        uint32_t a[4];
        a[0] = __ldg(arow + (size_t)lh * 192 + kw + lq);
        a[1] = __ldg(arow + (size_t)(lh + 8) * 192 + kw + lq);
        a[2] = __ldg(arow + (size_t)lh * 192 + kw + 4 + lq);
        a[3] = __ldg(arow + (size_t)(lh + 8) * 192 + kw + 4 + lq);
        #pragma unroll
        for (int j = 0; j < 4; j++) {
            uint32_t bfr[2];
            bfr[0] = __ldg(&g_W2bt32[(8 * j + lh) * 192 + kw + lq]);
            bfr[1] = __ldg(&g_W2bt32[(8 * j + lh) * 192 + kw + 4 + lq]);
            mma16(acc[j], a, bfr);
        }
    }

    {
        int r0 = wid * 16 + lh, r1 = r0 + 8;
        float rs0 = g_rstd[(size_t)b * TT + t0 + r0];
        float rs1 = g_rstd[(size_t)b * TT + t0 + r1];
        #pragma unroll
        for (int j = 0; j < 4; j++) {
            int oc = 8 * j + 2 * lq;
            sm1[r0 * 33 + oc]     = fmaxf(fmaf(acc[j][0], rs0, b_mix1[oc]), 0.f);
            sm1[r0 * 33 + oc + 1] = fmaxf(fmaf(acc[j][1], rs0, b_mix1[oc + 1]), 0.f);
            sm1[r1 * 33 + oc]     = fmaxf(fmaf(acc[j][2], rs1, b_mix1[oc]), 0.f);
            sm1[r1 * 33 + oc + 1] = fmaxf(fmaf(acc[j][3], rs1, b_mix1[oc + 1]), 0.f);
        }
    }
    __syncthreads();

    int r2 = tid >> 1;
    int oh = (tid & 1) * 16;
    float m2[16];
    #pragma unroll
    for (int o = 0; o < 16; o++) m2[o] = b_mix2[oh + o];
    #pragma unroll 4
    for (int i = 0; i < MIXD; i++) {
        float m = sm1[r2 * 33 + i];
        #pragma unroll
        for (int o = 0; o < 16; o++) m2[o] = fmaf(m, swm2[i * MIXD + oh + o], m2[o]);
    }
    #pragma unroll
    for (int o = 0; o < 16; o++) m2[o] = fmaxf(m2[o], 0.f);
    __syncthreads();
    #pragma unroll
    for (int o = 0; o < 16; o++) sm1[r2 * 33 + oh + o] = m2[o];
    __syncthreads();

    for (int s = 64; s >= 1; s >>= 1) {
        for (int idx = tid; idx < s * 32; idx += 256) {
            int r = idx >> 5, o = idx & 31;
            sm1[r * 33 + o] += sm1[(r + s) * 33 + o];
        }
        __syncthreads();
    }
    if (tid < MIXD) g_part[((size_t)b * 32 + blockIdx.x) * MIXD + tid] = sm1[tid];
}

// ---------------- kF: final mean + w_out ----------------
__global__ void kF(const float* __restrict__ w_out, const float* __restrict__ b_out,
                   float* __restrict__ out) {
    int b = threadIdx.x;
    if (b < BB) {
        float s = 0.f;
        for (int o = 0; o < MIXD; o++) {
            float a = 0.f;
            for (int blk = 0; blk < 32; blk++) a += g_part[((size_t)b * 32 + blk) * MIXD + o];
            s = fmaf(a * (1.f / (float)TT), w_out[o], s);
        }
        out[b] = s + b_out[0];
    }
}

extern "C" void kernel_launch(void* const* d_in, const int* in_sizes, int n_in,
                              void* d_out, int out_size) {
    const float* x        = (const float*)d_in[0];
    const float* mic_pos  = (const float*)d_in[1];
    const float* w_in     = (const float*)d_in[2];
    const float* b_in     = (const float*)d_in[3];
    const float* w_mic    = (const float*)d_in[4];
    const float* b_mic    = (const float*)d_in[5];
    const float* w_inproj = (const float*)d_in[6];
    const float* conv_w   = (const float*)d_in[7];
    const float* conv_b   = (const float*)d_in[8];
    const float* dt_bias  = (const float*)d_in[9];
    const float* A_log    = (const float*)d_in[10];
    const float* D_skip   = (const float*)d_in[11];
    const float* norm_w   = (const float*)d_in[12];
    const float* w_outproj= (const float*)d_in[13];
    const float* w_mix1   = (const float*)d_in[14];
    const float* b_mix1   = (const float*)d_in[15];
    const float* w_mix2   = (const float*)d_in[16];
    const float* b_mix2   = (const float*)d_in[17];
    const float* w_out    = (const float*)d_in[18];
    const float* b_out    = (const float*)d_in[19];
    float* out = (float*)d_out;

    cudaFuncSetAttribute(kC, cudaFuncAttributeMaxDynamicSharedMemorySize, KC_SMEM_FLOATS * 4);

    k0a<<<1, 256>>>(mic_pos, w_mic, b_mic, b_in, A_log);
    k0b<<<(4 * DPROJ + BB * DPROJ + 32 * 192 + 255) / 256, 256>>>(w_in, w_inproj, w_outproj, w_mix1, norm_w);
    k1<<<dim3(32, 16), 128>>>(x, conv_w, conv_b, dt_bias);
    kA<<<dim3(NC, BB), 192>>>();
    kB<<<dim3(128, 4), 384>>>();
    kC<<<dim3(NC, BB), 256, KC_SMEM_FLOATS * 4>>>(D_skip, x);
    kD2<<<dim3(32, BB), 256>>>(b_mix1, w_mix2, b_mix2);
    kF<<<1, 32>>>(w_out, b_out, out);
}

// round 16
// speedup vs baseline: 1.1148x; 1.1148x over previous
#include <cuda_runtime.h>
#include <cuda_bf16.h>
#include <math.h>
#include <stdint.h>

#define BB 16
#define TT 4096
#define DINNER 384
#define NH 8
#define HD 48
#define DS 64
#define DPROJ 904
#define NC 64
#define CS 64
#define MIXD 32

// ---------------- scratch (static device arrays; no runtime alloc) ----------
__device__ float g_W1[4 * DPROJ];            // w_in @ w_inproj
__device__ float g_mvec[BB * DPROJ];         // (b_in + relu(mic)) @ w_inproj
__device__ uint32_t g_W2bt32[32 * 192];      // bf16x2 [o][dpair]
__device__ float g_hb[BB * 192];
__device__ float g_A[NH];
__device__ uint32_t g_xbf[(size_t)BB * TT * 192];  // silu(conv) xs, bf16x2 pairs along p
__device__ float g_bc[(size_t)BB * TT * 128];      // B(64) | C(64) fp32
__device__ float g_dt[(size_t)BB * TT * NH];
__device__ float g_la[(size_t)BB * TT * NH];       // log-decay = dt*A
__device__ uint32_t g_Sbf[(size_t)128 * NC * HD * 32]; // chunk states bf16x2 (pairs along n) -> h_in in place
__device__ float g_Dc[128 * NC];
__device__ uint32_t g_ybf32[(size_t)BB * TT * 192];    // gated y, bf16x2
__device__ float g_rstd[BB * TT];
__device__ float g_part[2048 * MIXD];

__device__ __forceinline__ float siluf(float v) {
    if (fabsf(v) < 0.25f) {
        float z2 = v * v;
        float sig = 0.5f + v * (0.25f + z2 * (-(1.f / 48.f) + z2 * (1.f / 480.f)));
        return v * sig;
    }
    return __fdividef(v, 1.f + __expf(-v));
}
__device__ __forceinline__ float softplusf(float v) { return v > 20.f ? v : __logf(1.f + __expf(v)); }

__device__ __forceinline__ uint32_t packbf(float lo, float hi) {
    uint32_t w;
    asm("cvt.rn.bf16x2.f32 %0, %1, %2;" : "=r"(w) : "f"(hi), "f"(lo));
    return w;
}
__device__ __forceinline__ float2 unpackbf(uint32_t w) {
    return make_float2(__uint_as_float(w << 16), __uint_as_float(w & 0xffff0000u));
}
__device__ __forceinline__ float bfh(uint16_t v) {
    return __uint_as_float(((uint32_t)v) << 16);
}
__device__ __forceinline__ uint16_t bf16b(float v) {
    __nv_bfloat16 h = __float2bfloat16(v);
    return *reinterpret_cast<uint16_t*>(&h);
}

__device__ __forceinline__ void mma16(float d[4], const uint32_t a[4], const uint32_t b[2]) {
    asm volatile(
        "mma.sync.aligned.m16n8k16.row.col.f32.bf16.bf16.f32 "
        "{%0,%1,%2,%3},{%4,%5,%6,%7},{%8,%9},{%0,%1,%2,%3};\n"
        : "+f"(d[0]), "+f"(d[1]), "+f"(d[2]), "+f"(d[3])
        : "r"(a[0]), "r"(a[1]), "r"(a[2]), "r"(a[3]),
          "r"(b[0]), "r"(b[1]));
}

// ---------------- k0a: mic MLP + A ----------------
__global__ void k0a(const float* __restrict__ mic_pos, const float* __restrict__ w_mic,
                    const float* __restrict__ b_mic, const float* __restrict__ b_in,
                    const float* __restrict__ A_log) {
    int tid = threadIdx.x;
    for (int i = tid; i < BB * 192; i += 256) {
        int b = i / 192, d = i % 192;
        float s = b_mic[d];
        #pragma unroll
        for (int j = 0; j < 12; j++) s = fmaf(mic_pos[b * 12 + j], w_mic[j * 192 + d], s);
        g_hb[i] = b_in[d] + fmaxf(s, 0.f);
    }
    if (tid < NH) g_A[tid] = -expf(A_log[tid]);
}

// ---------------- k0b: folded weights ----------------
__global__ void k0b(const float* __restrict__ w_in, const float* __restrict__ w_inproj,
                    const float* __restrict__ w_outproj, const float* __restrict__ w_mix1,
                    const float* __restrict__ norm_w) {
    int i = blockIdx.x * 256 + threadIdx.x;
    if (i < 4 * DPROJ) {
        int j = i / DPROJ, d = i % DPROJ;
        float s = 0.f;
        for (int m = 0; m < 192; m++) s = fmaf(w_in[j * 192 + m], w_inproj[m * DPROJ + d], s);
        g_W1[i] = s;
    } else if (i < 4 * DPROJ + BB * DPROJ) {
        int ii = i - 4 * DPROJ;
        int b = ii / DPROJ, d = ii % DPROJ;
        float s = 0.f;
        for (int m = 0; m < 192; m++) s = fmaf(g_hb[b * 192 + m], w_inproj[m * DPROJ + d], s);
        g_mvec[ii] = s;
    } else if (i < 4 * DPROJ + BB * DPROJ + 32 * 192) {
        int ii = i - (4 * DPROJ + BB * DPROJ);
        int o = ii / 192, kw = ii % 192;
        int d0 = 2 * kw, d1 = d0 + 1;
        float s0 = 0.f, s1 = 0.f;
        for (int m = 0; m < 192; m++) {
            s0 = fmaf(w_outproj[d0 * 192 + m], w_mix1[m * MIXD + o], s0);
            s1 = fmaf(w_outproj[d1 * 192 + m], w_mix1[m * MIXD + o], s1);
        }
        g_W2bt32[o * 192 + kw] = packbf(s0 * norm_w[d0], s1 * norm_w[d1]);
    }
}

// ---------------- k1: fused inproj + conv4 + silu + dt/la ----------------
// grid (32, 16) block 128 : thread = one t
__global__ void k1(const float* __restrict__ x, const float* __restrict__ conv_w,
                   const float* __restrict__ conv_b, const float* __restrict__ dt_bias) {
    __shared__ float sW1[4 * 520];   // proj dims 384..903
    __shared__ float smv[520];
    __shared__ float scw[512 * 4];
    __shared__ float scb[512];
    __shared__ float sx4[131 * 4];
    __shared__ float sraw[131 * 33];

    int tid = threadIdx.x;
    int b = blockIdx.y;
    int t0 = blockIdx.x * 128;

    for (int i = tid; i < 4 * 520; i += 128) sW1[i] = g_W1[(i / 520) * DPROJ + 384 + (i % 520)];
    for (int i = tid; i < 520; i += 128) smv[i] = g_mvec[b * DPROJ + 384 + i];
    for (int i = tid; i < 512 * 4; i += 128) scw[i] = conv_w[i];
    for (int i = tid; i < 512; i += 128) scb[i] = conv_b[i];
    for (int i = tid; i < 131 * 4; i += 128) {
        int r = i >> 2, j = i & 3;
        int t = t0 + r - 3;
        sx4[i] = (t >= 0) ? x[((size_t)b * TT + t) * 4 + j] : 0.f;
    }

    int t = t0 + tid;
    for (int c16 = 0; c16 < 16; c16++) {
        __syncthreads();
        for (int i = tid; i < 131 * 32; i += 128) {
            int r = i >> 5, dc = i & 31;
            int dd = c16 * 32 + dc;
            float v = 0.f;
            if (t0 + r - 3 >= 0) {
                v = smv[dd];
                #pragma unroll
                for (int j = 0; j < 4; j++) v = fmaf(sx4[r * 4 + j], sW1[j * 520 + dd], v);
            }
            sraw[r * 33 + dc] = v;
        }
        __syncthreads();
        float v[32];
        #pragma unroll
        for (int dc = 0; dc < 32; dc++) {
            int dd = c16 * 32 + dc;
            float a = scb[dd];
            #pragma unroll
            for (int k = 0; k < 4; k++) a = fmaf(sraw[(tid + k) * 33 + dc], scw[dd * 4 + k], a);
            v[dc] = siluf(a);
        }
        if (c16 < 12) {
            uint32_t* dst = g_xbf + ((size_t)b * TT + t) * 192 + c16 * 16;
            #pragma unroll
            for (int q = 0; q < 4; q++) {
                uint4 w;
                w.x = packbf(v[8 * q + 0], v[8 * q + 1]);
                w.y = packbf(v[8 * q + 2], v[8 * q + 3]);
                w.z = packbf(v[8 * q + 4], v[8 * q + 5]);
                w.w = packbf(v[8 * q + 6], v[8 * q + 7]);
                ((uint4*)dst)[q] = w;
            }
        } else {
            float* dst = g_bc + ((size_t)b * TT + t) * 128 + (c16 - 12) * 32;
            #pragma unroll
            for (int q = 0; q < 8; q++)
                ((float4*)dst)[q] = make_float4(v[4 * q], v[4 * q + 1], v[4 * q + 2], v[4 * q + 3]);
        }
    }

    // dt path (proj dims 896..903 via sW1 dims 512..519)
    #pragma unroll
    for (int hh = 0; hh < NH; hh++) {
        int dd = 512 + hh;
        float v = smv[dd];
        #pragma unroll
        for (int j = 0; j < 4; j++) v = fmaf(sx4[(tid + 3) * 4 + j], sW1[j * 520 + dd], v);
        float dt = softplusf(v + dt_bias[hh]);
        size_t o = ((size_t)b * TT + t) * NH + hh;
        g_dt[o] = dt;
        g_la[o] = dt * g_A[hh];
    }
}

// ---------------- kA: chunk-local end states via bf16 mma16, all heads/block
// grid (NC, BB) block 192 (6 warps): warp = (p-strip w%3, n-half w/3)
__global__ __launch_bounds__(192) void kA() {
    __shared__ uint32_t sXw[48 * 36];   // bf16x2 [p][t-pair], word stride 36
    __shared__ uint32_t sBn[64 * 36];   // bf16x2 [n][t-pair], word stride 36
    __shared__ float sCS[8 * 64];       // [h][t] inclusive log-decay prefix
    __shared__ float sDT[8 * 64];       // [h][t]

    int c = blockIdx.x, b = blockIdx.y;
    int tid = threadIdx.x;
    int wid = tid >> 5, lane = tid & 31;
    int lq = lane & 3, lh = lane >> 2;
    int t0 = c * CS;
    uint16_t* shX = (uint16_t*)sXw;
    uint16_t* shB = (uint16_t*)sBn;

    // la/dt for all heads, transpose to [h][t]
    if (tid < 128) {
        const float* lap = g_la + ((size_t)b * TT + t0) * NH;
        const float* dtp = g_dt + ((size_t)b * TT + t0) * NH;
        float4 v = ((const float4*)lap)[tid];
        float4 w = ((const float4*)dtp)[tid];
        int j0 = tid * 4;
        #pragma unroll
        for (int u = 0; u < 4; u++) {
            int j = j0 + u;
            int t = j >> 3, h = j & 7;
            sCS[h * 64 + t] = (&v.x)[u];
            sDT[h * 64 + t] = (&w.x)[u];
        }
    }

    // B staged ONCE as bf16 [n][t] (16-bit transpose stores)
    const float* bp = g_bc + ((size_t)b * TT + t0) * 128;
    for (int i = tid; i < CS * 16; i += 192) {
        int t = i >> 4, nq = i & 15;
        float4 v = ((const float4*)(bp + (size_t)t * 128))[nq];
        int n0 = nq * 4;
        shB[(n0 + 0) * 72 + t] = bf16b(v.x);
        shB[(n0 + 1) * 72 + t] = bf16b(v.y);
        shB[(n0 + 2) * 72 + t] = bf16b(v.z);
        shB[(n0 + 3) * 72 + t] = bf16b(v.w);
    }
    __syncthreads();

    // per-head inclusive log-decay prefix scans (6 warps cover 8 heads)
    for (int hh = wid; hh < NH; hh += 6) {
        float a0 = sCS[hh * 64 + 2 * lane], a1 = sCS[hh * 64 + 2 * lane + 1];
        float ps = a0 + a1;
        #pragma unroll
        for (int off = 1; off < 32; off <<= 1) {
            float v = __shfl_up_sync(0xffffffffu, ps, off);
            if (lane >= off) ps += v;
        }
        sCS[hh * 64 + 2 * lane + 1] = ps;
        sCS[hh * 64 + 2 * lane]     = ps - a1;
    }
    __syncthreads();

    int p0 = (wid % 3) * 16;
    int nb = (wid / 3) * 32;

    for (int h = 0; h < NH; h++) {
        const float* csh = sCS + h * 64;
        const float* dth = sDT + h * 64;
        float cstot = csh[CS - 1];

        // stage this head's x slice as bf16 [p][t], scaled by w(t)=exp(cstot-cs[t])*dt[t]
        const uint32_t* xp = g_xbf + ((size_t)b * TT + t0) * 192 + h * 24;
        for (int i = tid; i < CS * 6; i += 192) {
            int t = i / 6, col = i % 6;
            float wgt = __expf(cstot - csh[t]) * dth[t];
            uint4 w4 = ((const uint4*)(xp + (size_t)t * 192))[col];
            uint32_t ws[4] = {w4.x, w4.y, w4.z, w4.w};
            int p0w = col * 8;
            #pragma unroll
            for (int u = 0; u < 4; u++) {
                float2 q = unpackbf(ws[u]);
                int p = p0w + 2 * u;
                shX[p * 72 + t]       = bf16b(q.x * wgt);
                shX[(p + 1) * 72 + t] = bf16b(q.y * wgt);
            }
        }
        __syncthreads();

        // S[p][n] = sum_t Xw[t][p] * B[t][n]  (bf16 mma16: M=48, N=64, K=64)
        float acc[4][4];
        #pragma unroll
        for (int j = 0; j < 4; j++)
            #pragma unroll
            for (int e = 0; e < 4; e++) acc[j][e] = 0.f;

        #pragma unroll
        for (int k16 = 0; k16 < CS; k16 += 16) {
            int kw = k16 >> 1;
            uint32_t a[4];
            a[0] = sXw[(p0 + lh) * 36 + kw + lq];
            a[1] = sXw[(p0 + lh + 8) * 36 + kw + lq];
            a[2] = sXw[(p0 + lh) * 36 + kw + lq + 4];
            a[3] = sXw[(p0 + lh + 8) * 36 + kw + lq + 4];
            #pragma unroll
            for (int j = 0; j < 4; j++) {
                int n = nb + 8 * j + lh;
                uint32_t bfr[2];
                bfr[0] = sBn[n * 36 + kw + lq];
                bfr[1] = sBn[n * 36 + kw + lq + 4];
                mma16(acc[j], a, bfr);
            }
        }

        uint32_t* sp = g_Sbf + ((size_t)(b * NH + h) * NC + c) * 1536;
        #pragma unroll
        for (int j = 0; j < 4; j++) {
            int n0 = nb + 8 * j + 2 * lq;
            sp[(p0 + lh) * 32 + (n0 >> 1)]     = packbf(acc[j][0], acc[j][1]);
            sp[(p0 + lh + 8) * 32 + (n0 >> 1)] = packbf(acc[j][2], acc[j][3]);
        }
        if (tid == 0) g_Dc[(b * NH + h) * NC + c] = __expf(cstot);
        __syncthreads();   // sXw reads done before next head's staging
    }
}

// ---------------- kB: inter-chunk scan (fp32 regs, bf16 storage) ----------
// grid (128, 4) block 384 : thread owns 2 states (1 word), depth-2 prefetch
__global__ void kB() {
    int bh = blockIdx.x, q = blockIdx.y;
    int tid = threadIdx.x;
    float h0 = 0.f, h1 = 0.f;
    size_t base = (size_t)bh * NC * 1536 + (size_t)q * 384 + tid;
    uint32_t a0 = g_Sbf[base];
    uint32_t a1 = g_Sbf[base + 1536];
    float D0 = g_Dc[bh * NC];
    float D1 = g_Dc[bh * NC + 1];
    for (int c = 0; c < NC; c++) {
        uint32_t* sp = g_Sbf + base + (size_t)c * 1536;
        uint32_t an = 0u;
        float Dn = 0.f;
        if (c + 2 < NC) {
            an = sp[2 * 1536];
            Dn = g_Dc[bh * NC + c + 2];
        }
        float2 p = unpackbf(a0);
        sp[0] = packbf(h0, h1);
        h0 = fmaf(h0, D0, p.x);
        h1 = fmaf(h1, D0, p.y);
        a0 = a1; a1 = an; D0 = D1; D1 = Dn;
    }
}

// ---------------- kC: chunked SSD + fused gating/RMS-stats (all-bf16 mma) --
// grid (NC, BB) block 256 (8 warps), smem ~47.4 KB -> 4 CTAs/SM
#define STB 36
#define KC_G    0                        // G bf16 words [t][STB]   (2304)
#define KC_CB   (KC_G + 64 * STB)        // C bf16 [t][n-pair]      (2304)
#define KC_BB   (KC_CB + 64 * STB)       // B bf16 [s][n-pair]      (2304)
#define KC_XT   (KC_BB + 64 * STB)       // x^T bf16 [p:48][s-pair] (1728)
#define KC_SCS  (KC_XT + 48 * STB)       // 8*64
#define KC_SDT  (KC_SCS + 512)           // 8*64
#define KC_W1Z  (KC_SDT + 512)           // 4*384
#define KC_MVZ  (KC_W1Z + 1536)          // 384
#define KC_X4   (KC_MVZ + 384)           // 64*4
#define KC_SMEM_FLOATS (KC_X4 + 256)

__global__ __launch_bounds__(256) void kC(const float* __restrict__ D_skip,
                                          const float* __restrict__ xin) {
    extern __shared__ float sm[];
    uint32_t* smu = (uint32_t*)sm;
    uint16_t* smh = (uint16_t*)sm;
    float* sCS  = sm + KC_SCS;
    float* sDT  = sm + KC_SDT;
    float* sW1z = sm + KC_W1Z;
    float* smvz = sm + KC_MVZ;
    float* sx4  = sm + KC_X4;

    int c = blockIdx.x, b = blockIdx.y;
    int tid = threadIdx.x;
    int wid = tid >> 5, lane = tid & 31;
    int lq = lane & 3, lh = lane >> 2;
    int t0c = c * CS;

    if (tid < 128) {
        const float* lap = g_la + ((size_t)b * TT + t0c) * NH;
        const float* dtp = g_dt + ((size_t)b * TT + t0c) * NH;
        float4 v = ((const float4*)lap)[tid];
        float4 w = ((const float4*)dtp)[tid];
        int j0 = tid * 4;
        #pragma unroll
        for (int u = 0; u < 4; u++) {
            int j = j0 + u;
            int t = j >> 3, h = j & 7;
            sCS[h * 64 + t] = (&v.x)[u];
            sDT[h * 64 + t] = (&w.x)[u];
        }
    }
    for (int i = tid; i < 4 * DINNER; i += 256) sW1z[i] = g_W1[(i / DINNER) * DPROJ + (i % DINNER)];
    for (int i = tid; i < DINNER; i += 256) smvz[i] = g_mvec[b * DPROJ + i];
    if (tid < 256) {
        int r = tid >> 2, j = tid & 3;
        sx4[tid] = xin[((size_t)b * TT + t0c + r) * 4 + j];
    }

    // B,C load: bf16-packed row layouts [s][n-pair]
    const float* bp = g_bc + ((size_t)b * TT + t0c) * 128;
    for (int i = tid; i < CS * 16; i += 256) {
        int s = i >> 4, nq = i & 15;
        float4 v = ((const float4*)(bp + (size_t)s * 128))[nq];          // B[s][n]
        smu[KC_BB + s * STB + 2 * nq]     = packbf(v.x, v.y);
        smu[KC_BB + s * STB + 2 * nq + 1] = packbf(v.z, v.w);
        float4 w = ((const float4*)(bp + (size_t)s * 128))[nq + 16];     // C[s][n]
        smu[KC_CB + s * STB + 2 * nq]     = packbf(w.x, w.y);
        smu[KC_CB + s * STB + 2 * nq + 1] = packbf(w.z, w.w);
    }
    __syncthreads();

    // per-head inclusive log-decay prefix (warp w = head w)
    {
        float a0 = sCS[wid * 64 + 2 * lane];
        float a1 = sCS[wid * 64 + 2 * lane + 1];
        float ps = a0 + a1;
        #pragma unroll
        for (int off = 1; off < 32; off <<= 1) {
            float v = __shfl_up_sync(0xffffffffu, ps, off);
            if (lane >= off) ps += v;
        }
        sCS[wid * 64 + 2 * lane + 1] = ps;
        sCS[wid * 64 + 2 * lane]     = ps - a1;
    }

    int t0 = (wid & 3) * 16;
    int sb = (wid >> 2) * 32;
    int pb = (wid >> 2) * 24;

    float xr0[4], xr1[4];
    #pragma unroll
    for (int u = 0; u < 4; u++) {
        xr0[u] = sx4[(t0 + lh) * 4 + u];
        xr1[u] = sx4[(t0 + lh + 8) * 4 + u];
    }
    __syncthreads();   // prefix scan visible to all warps

    // GEMM1 (bf16, shared across heads): Graw[t][s] = sum_n C[t][n]*B[s][n]
    float g1[4][4];
    #pragma unroll
    for (int j = 0; j < 4; j++)
        #pragma unroll
        for (int e = 0; e < 4; e++) g1[j][e] = 0.f;

    #pragma unroll
    for (int k16 = 0; k16 < DS; k16 += 16) {
        int kw = k16 >> 1;
        uint32_t a[4];
        a[0] = smu[KC_CB + (t0 + lh) * STB + kw + lq];
        a[1] = smu[KC_CB + (t0 + lh + 8) * STB + kw + lq];
        a[2] = smu[KC_CB + (t0 + lh) * STB + kw + lq + 4];
        a[3] = smu[KC_CB + (t0 + lh + 8) * STB + kw + lq + 4];
        #pragma unroll
        for (int j = 0; j < 4; j++) {
            int s = sb + 8 * j + lh;
            uint32_t bfr[2];
            bfr[0] = smu[KC_BB + s * STB + kw + lq];
            bfr[1] = smu[KC_BB + s * STB + kw + lq + 4];
            mma16(g1[j], a, bfr);
        }
    }

    float ss0 = 0.f, ss1 = 0.f;
    uint32_t* ybase = g_ybf32 + ((size_t)b * TT + t0c) * 192;

    for (int h = 0; h < NH; h++) {
        __syncthreads();   // prior head's reads of G/xT done

        // build x^T [p][s-pair] bf16 for this head (16-bit smem stores)
        const uint32_t* xp = g_xbf + ((size_t)b * TT + t0c) * 192 + h * 24;
        for (int i = tid; i < CS * 6; i += 256) {
            int s = i / 6, col = i % 6;
            uint4 w4 = ((const uint4*)(xp + (size_t)s * 192))[col];
            int p0w = col * 8;
            int half = s & 1, sw = s >> 1;
            uint32_t ws[4] = {w4.x, w4.y, w4.z, w4.w};
            #pragma unroll
            for (int u = 0; u < 4; u++) {
                int p = p0w + 2 * u;
                smh[(KC_XT + p * STB + sw) * 2 + half]       = (uint16_t)(ws[u] & 0xffffu);
                smh[(KC_XT + (p + 1) * STB + sw) * 2 + half] = (uint16_t)(ws[u] >> 16);
            }
        }

        // mask+scale Graw with this head's decay, store bf16 G [t][s-pair]
        const float* csh = sCS + h * 64;
        const float* dth = sDT + h * 64;
        {
            float cs_r0 = csh[t0 + lh], cs_r1 = csh[t0 + lh + 8];
            #pragma unroll
            for (int j = 0; j < 4; j++) {
                int c0 = sb + 8 * j + 2 * lq;
                float cs_c0 = csh[c0], cs_c1 = csh[c0 + 1];
                float dt_c0 = dth[c0], dt_c1 = dth[c0 + 1];
                int r0 = t0 + lh, r1 = r0 + 8;
                float m00 = (c0 <= r0) ? __expf(cs_r0 - cs_c0) * dt_c0 : 0.f;
                float m01 = (c0 + 1 <= r0) ? __expf(cs_r0 - cs_c1) * dt_c1 : 0.f;
                float m10 = (c0 <= r1) ? __expf(cs_r1 - cs_c0) * dt_c0 : 0.f;
                float m11 = (c0 + 1 <= r1) ? __expf(cs_r1 - cs_c1) * dt_c1 : 0.f;
                int cw = c0 >> 1;
                smu[KC_G + r0 * STB + cw] = packbf(g1[j][0] * m00, g1[j][1] * m01);
                smu[KC_G + r1 * STB + cw] = packbf(g1[j][2] * m10, g1[j][3] * m11);
            }
        }
        __syncthreads();

        // GEMM2 (bf16): Yintra[t][p] = sum_s G[t][s]*x[s][p]
        // GEMM3 (bf16): Yinter[t][p] = sum_n C[t][n]*hin[n][p]  (B fragments direct from global)
        float accA[3][4], accB[3][4];
        #pragma unroll
        for (int j = 0; j < 3; j++)
            #pragma unroll
            for (int e = 0; e < 4; e++) { accA[j][e] = 0.f; accB[j][e] = 0.f; }

        const uint32_t* hp = g_Sbf + ((size_t)(b * NH + h) * NC + c) * 1536;
        #pragma unroll
        for (int k16 = 0; k16 < 64; k16 += 16) {
            int kw = k16 >> 1;
            uint32_t a[4];
            a[0] = smu[KC_G + (t0 + lh) * STB + kw + lq];
            a[1] = smu[KC_G + (t0 + lh + 8) * STB + kw + lq];
            a[2] = smu[KC_G + (t0 + lh) * STB + kw + lq + 4];
            a[3] = smu[KC_G + (t0 + lh + 8) * STB + kw + lq + 4];
            #pragma unroll
            for (int j = 0; j < 3; j++) {
                int p = pb + 8 * j + lh;
                uint32_t bfr[2];
                bfr[0] = smu[KC_XT + p * STB + kw + lq];
                bfr[1] = smu[KC_XT + p * STB + kw + lq + 4];
                mma16(accA[j], a, bfr);
            }
            uint32_t a2[4];
            a2[0] = smu[KC_CB + (t0 + lh) * STB + kw + lq];
            a2[1] = smu[KC_CB + (t0 + lh + 8) * STB + kw + lq];
            a2[2] = smu[KC_CB + (t0 + lh) * STB + kw + lq + 4];
            a2[3] = smu[KC_CB + (t0 + lh + 8) * STB + kw + lq + 4];
            #pragma unroll
            for (int j = 0; j < 3; j++) {
                int p = pb + 8 * j + lh;
                uint32_t bfr[2];
                bfr[0] = __ldg(hp + p * 32 + kw + lq);
                bfr[1] = __ldg(hp + p * 32 + kw + lq + 4);
                mma16(accB[j], a2, bfr);
            }
        }

        // epilogue: y = intra + exp(cs)*inter + D*x; gate; accumulate ss; store bf16
        float dskip = D_skip[h];
        float et0 = __expf(csh[t0 + lh]);
        float et1 = __expf(csh[t0 + lh + 8]);
        #pragma unroll
        for (int j = 0; j < 3; j++) {
            int p0c = pb + 8 * j + 2 * lq;
            int r0 = t0 + lh, r1 = r0 + 8;
            int dd = h * HD + p0c;
            float x00 = bfh(smh[(KC_XT + p0c * STB + (r0 >> 1)) * 2 + (r0 & 1)]);
            float x01 = bfh(smh[(KC_XT + (p0c + 1) * STB + (r0 >> 1)) * 2 + (r0 & 1)]);
            float x10 = bfh(smh[(KC_XT + p0c * STB + (r1 >> 1)) * 2 + (r1 & 1)]);
            float x11 = bfh(smh[(KC_XT + (p0c + 1) * STB + (r1 >> 1)) * 2 + (r1 & 1)]);
            float y00 = accA[j][0] + et0 * accB[j][0] + dskip * x00;
            float y01 = accA[j][1] + et0 * accB[j][1] + dskip * x01;
            float y10 = accA[j][2] + et1 * accB[j][2] + dskip * x10;
            float y11 = accA[j][3] + et1 * accB[j][3] + dskip * x11;
            float w0a = sW1z[dd],            w0b = sW1z[dd + 1];
            float w1a = sW1z[DINNER + dd],   w1b = sW1z[DINNER + dd + 1];
            float w2a = sW1z[2*DINNER + dd], w2b = sW1z[2*DINNER + dd + 1];
            float w3a = sW1z[3*DINNER + dd], w3b = sW1z[3*DINNER + dd + 1];
            float mva = smvz[dd], mvb = smvz[dd + 1];
            float za0 = fmaf(xr0[3], w3a, fmaf(xr0[2], w2a, fmaf(xr0[1], w1a, fmaf(xr0[0], w0a, mva))));
            float zb0 = fmaf(xr0[3], w3b, fmaf(xr0[2], w2b, fmaf(xr0[1], w1b, fmaf(xr0[0], w0b, mvb))));
            float za1 = fmaf(xr1[3], w3a, fmaf(xr1[2], w2a, fmaf(xr1[1], w1a, fmaf(xr1[0], w0a, mva))));
            float zb1 = fmaf(xr1[3], w3b, fmaf(xr1[2], w2b, fmaf(xr1[1], w1b, fmaf(xr1[0], w0b, mvb))));
            float g00 = y00 * siluf(za0);
            float g01 = y01 * siluf(zb0);
            float g10 = y10 * siluf(za1);
            float g11 = y11 * siluf(zb1);
            ss0 = fmaf(g00, g00, fmaf(g01, g01, ss0));
            ss1 = fmaf(g10, g10, fmaf(g11, g11, ss1));
            ybase[(size_t)r0 * 192 + (dd >> 1)] = packbf(g00, g01);
            ybase[(size_t)r1 * 192 + (dd >> 1)] = packbf(g10, g11);
        }
    }

    // row sum-of-squares -> rstd   (reuse sCS region)
    __syncthreads();
    ss0 += __shfl_xor_sync(0xffffffffu, ss0, 1);
    ss0 += __shfl_xor_sync(0xffffffffu, ss0, 2);
    ss1 += __shfl_xor_sync(0xffffffffu, ss1, 1);
    ss1 += __shfl_xor_sync(0xffffffffu, ss1, 2);
    if (lq == 0) {
        sCS[(wid >> 2) * 64 + t0 + lh]     = ss0;
        sCS[(wid >> 2) * 64 + t0 + lh + 8] = ss1;
    }
    __syncthreads();
    if (tid < 64) {
        float s = sCS[tid] + sCS[64 + tid];
        g_rstd[(size_t)b * TT + t0c + tid] = rsqrtf(s * (1.f / DINNER) + 1e-5f);
    }
}

// ---------------- kD2: bf16 mma GEMM(W2) + rstd + mix2 + partial ----------
// grid (32, BB) block 256 (8 warps), 128 rows/block
__global__ __launch_bounds__(256) void kD2(const float* __restrict__ b_mix1,
                   const float* __restrict__ w_mix2, const float* __restrict__ b_mix2) {
    __shared__ float sm1[128 * 33];
    __shared__ float swm2[MIXD * MIXD];

    int tid = threadIdx.x;
    int wid = tid >> 5, lane = tid & 31;
    int lq = lane & 3, lh = lane >> 2;
    int b = blockIdx.y;
    int t0 = blockIdx.x * 128;

    for (int i = tid; i < MIXD * MIXD; i += 256) swm2[i] = w_mix2[i];

    const uint32_t* arow = g_ybf32 + ((size_t)b * TT + t0 + wid * 16) * 192;
    float acc[4][4];
    #pragma unroll
    for (int j = 0; j < 4; j++)
        #pragma unroll
        for (int e = 0; e < 4; e++) acc[j][e] = 0.f;

    #pragma unroll 4
    for (int k16 = 0; k16 < DINNER; k16 += 16) {
        int kw = k16 >> 1;
        uint32_t a[4];
        a[0] = __ldg(arow + (size_t)lh * 192 + kw + lq);
        a[1] = __ldg(arow + (size_t)(lh + 8) * 192 + kw + lq);
        a[2] = __ldg(arow + (size_t)lh * 192 + kw + 4 + lq);
        a[3] = __ldg(arow + (size_t)(lh + 8) * 192 + kw + 4 + lq);
        #pragma unroll
        for (int j = 0; j < 4; j++) {
            uint32_t bfr[2];
            bfr[0] = __ldg(&g_W2bt32[(8 * j + lh) * 192 + kw + lq]);
            bfr[1] = __ldg(&g_W2bt32[(8 * j + lh) * 192 + kw + 4 + lq]);
            mma16(acc[j], a, bfr);
        }
    }

    {
        int r0 = wid * 16 + lh, r1 = r0 + 8;
        float rs0 = g_rstd[(size_t)b * TT + t0 + r0];
        float rs1 = g_rstd[(size_t)b * TT + t0 + r1];
        #pragma unroll
        for (int j = 0; j < 4; j++) {
            int oc = 8 * j + 2 * lq;
            sm1[r0 * 33 + oc]     = fmaxf(fmaf(acc[j][0], rs0, b_mix1[oc]), 0.f);
            sm1[r0 * 33 + oc + 1] = fmaxf(fmaf(acc[j][1], rs0, b_mix1[oc + 1]), 0.f);
            sm1[r1 * 33 + oc]     = fmaxf(fmaf(acc[j][2], rs1, b_mix1[oc]), 0.f);
            sm1[r1 * 33 + oc + 1] = fmaxf(fmaf(acc[j][3], rs1, b_mix1[oc + 1]), 0.f);
        }
    }
    __syncthreads();

    int r2 = tid >> 1;
    int oh = (tid & 1) * 16;
    float m2[16];
    #pragma unroll
    for (int o = 0; o < 16; o++) m2[o] = b_mix2[oh + o];
    #pragma unroll 4
    for (int i = 0; i < MIXD; i++) {
        float m = sm1[r2 * 33 + i];
        #pragma unroll
        for (int o = 0; o < 16; o++) m2[o] = fmaf(m, swm2[i * MIXD + oh + o], m2[o]);
    }
    #pragma unroll
    for (int o = 0; o < 16; o++) m2[o] = fmaxf(m2[o], 0.f);
    __syncthreads();
    #pragma unroll
    for (int o = 0; o < 16; o++) sm1[r2 * 33 + oh + o] = m2[o];
    __syncthreads();

    // 2-phase grouped reduction over 128 rows: 8 groups of 16 (2 barriers total)
    {
        int o = tid & 31, rg = tid >> 5;
        float a = 0.f;
        #pragma unroll 4
        for (int r = rg * 16; r < rg * 16 + 16; r++) a += sm1[r * 33 + o];
        __syncthreads();
        sm1[rg * 33 + o] = a;
    }
    __syncthreads();
    if (tid < MIXD) {
        float s = 0.f;
        #pragma unroll
        for (int rg = 0; rg < 8; rg++) s += sm1[rg * 33 + tid];
        g_part[((size_t)b * 32 + blockIdx.x) * MIXD + tid] = s;
    }
}

// ---------------- kF: final mean + w_out ----------------
__global__ void kF(const float* __restrict__ w_out, const float* __restrict__ b_out,
                   float* __restrict__ out) {
    int b = threadIdx.x;
    if (b < BB) {
        float s = 0.f;
        for (int o = 0; o < MIXD; o++) {
            float a = 0.f;
            for (int blk = 0; blk < 32; blk++) a += g_part[((size_t)b * 32 + blk) * MIXD + o];
            s = fmaf(a * (1.f / (float)TT), w_out[o], s);
        }
        out[b] = s + b_out[0];
    }
}

extern "C" void kernel_launch(void* const* d_in, const int* in_sizes, int n_in,
                              void* d_out, int out_size) {
    const float* x        = (const float*)d_in[0];
    const float* mic_pos  = (const float*)d_in[1];
    const float* w_in     = (const float*)d_in[2];
    const float* b_in     = (const float*)d_in[3];
    const float* w_mic    = (const float*)d_in[4];
    const float* b_mic    = (const float*)d_in[5];
    const float* w_inproj = (const float*)d_in[6];
    const float* conv_w   = (const float*)d_in[7];
    const float* conv_b   = (const float*)d_in[8];
    const float* dt_bias  = (const float*)d_in[9];
    const float* A_log    = (const float*)d_in[10];
    const float* D_skip   = (const float*)d_in[11];
    const float* norm_w   = (const float*)d_in[12];
    const float* w_outproj= (const float*)d_in[13];
    const float* w_mix1   = (const float*)d_in[14];
    const float* b_mix1   = (const float*)d_in[15];
    const float* w_mix2   = (const float*)d_in[16];
    const float* b_mix2   = (const float*)d_in[17];
    const float* w_out    = (const float*)d_in[18];
    const float* b_out    = (const float*)d_in[19];
    float* out = (float*)d_out;

    cudaFuncSetAttribute(kC, cudaFuncAttributeMaxDynamicSharedMemorySize, KC_SMEM_FLOATS * 4);

    k0a<<<1, 256>>>(mic_pos, w_mic, b_mic, b_in, A_log);
    k0b<<<(4 * DPROJ + BB * DPROJ + 32 * 192 + 255) / 256, 256>>>(w_in, w_inproj, w_outproj, w_mix1, norm_w);
    k1<<<dim3(32, 16), 128>>>(x, conv_w, conv_b, dt_bias);
    kA<<<dim3(NC, BB), 192>>>();
    kB<<<dim3(128, 4), 384>>>();
    kC<<<dim3(NC, BB), 256, KC_SMEM_FLOATS * 4>>>(D_skip, x);
    kD2<<<dim3(32, BB), 256>>>(b_mix1, w_mix2, b_mix2);
    kF<<<1, 32>>>(w_out, b_out, out);
}